// round 14
// baseline (speedup 1.0000x reference)
#include <cuda_runtime.h>
#include <cuda_fp16.h>
#include <mma.h>
#include <math.h>
#include <stdint.h>

using namespace nvcuda;

// Problem constants
#define NTOKS   65536
#define NGROUPS 8
#define SPER    8192
#define SWIN    128
#define NWIN    64
#define NKV     192
#define HEADS   8

// ---------------- device scratch ----------------
__device__ __align__(1024) __half g_q   [(size_t)NTOKS * 512];
__device__ __align__(1024) __half g_akv [(size_t)NTOKS * 512];
__device__ __align__(1024) __half g_kv  [(size_t)NTOKS * 1024];
__device__ __align__(1024) __half g_attn[(size_t)NTOKS * 512];
__device__ __align__(1024) float  g_x1  [(size_t)NTOKS * 512];
__device__ __align__(1024) __half g_h1  [(size_t)NTOKS * 1024];
__device__ __align__(1024) __half g_wkv [1024 * 512];
__device__ __align__(1024) __half g_wo  [512 * 512];
__device__ __align__(1024) __half g_w1c [1024 * 512];
__device__ __align__(1024) __half g_w2  [512 * 1024];
__device__ float g_bcomb[1024];

// ---------------- helpers ----------------
__device__ __forceinline__ uint32_t smem_u32(const void* p) {
    uint32_t a;
    asm("{ .reg .u64 t; cvta.to.shared.u64 t, %1; cvt.u32.u64 %0, t; }" : "=r"(a) : "l"(p));
    return a;
}
__device__ __forceinline__ void cp16_s(uint32_t daddr, const void* src) {
    asm volatile("cp.async.cg.shared.global [%0], [%1], 16;\n" :: "r"(daddr), "l"(src));
}
__device__ __forceinline__ void cp16(void* dst, const void* src) { cp16_s(smem_u32(dst), src); }
__device__ __forceinline__ void cp_commit() { asm volatile("cp.async.commit_group;\n"); }
template<int N> __device__ __forceinline__ void cp_wait() {
    asm volatile("cp.async.wait_group %0;\n" :: "n"(N));
}
__device__ __forceinline__ void ldsm4(uint32_t& r0, uint32_t& r1, uint32_t& r2, uint32_t& r3,
                                      uint32_t addr) {
    asm volatile("ldmatrix.sync.aligned.m8n8.x4.shared.b16 {%0,%1,%2,%3}, [%4];"
                 : "=r"(r0), "=r"(r1), "=r"(r2), "=r"(r3) : "r"(addr));
}
__device__ __forceinline__ void ldsm4t(uint32_t& r0, uint32_t& r1, uint32_t& r2, uint32_t& r3,
                                       uint32_t addr) {
    asm volatile("ldmatrix.sync.aligned.m8n8.x4.trans.shared.b16 {%0,%1,%2,%3}, [%4];"
                 : "=r"(r0), "=r"(r1), "=r"(r2), "=r"(r3) : "r"(addr));
}
__device__ __forceinline__ void hmma(float* d, const uint32_t* a, const uint32_t* b) {
    asm volatile("mma.sync.aligned.m16n8k16.row.col.f32.f16.f16.f32 "
                 "{%0,%1,%2,%3},{%4,%5,%6,%7},{%8,%9},{%0,%1,%2,%3};"
                 : "+f"(d[0]), "+f"(d[1]), "+f"(d[2]), "+f"(d[3])
                 : "r"(a[0]), "r"(a[1]), "r"(a[2]), "r"(a[3]), "r"(b[0]), "r"(b[1]));
}
__device__ __forceinline__ uint32_t h2u(float a, float b) {
    __half2 t = __floats2half2_rn(a, b);
    return *(uint32_t*)&t;
}
// swizzled offset (halfs): rows of 64 halfs (128B), 16B chunk XOR row&7
__device__ __forceinline__ int swz(int row, int colh) {
    return row * 64 + ((((colh >> 3) ^ (row & 7)) << 3) | (colh & 7));
}

// ---------------- W_comb = W_emb @ W1, fp16 transposed ----------------
__global__ void __launch_bounds__(256)
wcomb_kernel(const float* __restrict__ We, const float* __restrict__ W1, __half* __restrict__ outT) {
    __shared__ float sa[64][65];
    __shared__ float sb[64][65];
    int bi = blockIdx.y * 64, bn = blockIdx.x * 64;
    int tid = threadIdx.x;
    int ti = (tid >> 4) * 4, tn = (tid & 15) * 4;
    float acc[4][4] = {};
    for (int j0 = 0; j0 < 512; j0 += 64) {
        for (int t = tid; t < 4096; t += 256) {
            int r = t >> 6, c = t & 63;
            sa[r][c] = We[(size_t)(bi + r) * 512 + j0 + c];
            sb[r][c] = W1[(size_t)(j0 + r) * 1024 + bn + c];
        }
        __syncthreads();
        for (int j = 0; j < 64; j++) {
            float b0 = sb[j][tn], b1 = sb[j][tn + 1], b2 = sb[j][tn + 2], b3 = sb[j][tn + 3];
            #pragma unroll
            for (int i = 0; i < 4; i++) {
                float av = sa[ti + i][j];
                acc[i][0] += av * b0; acc[i][1] += av * b1;
                acc[i][2] += av * b2; acc[i][3] += av * b3;
            }
        }
        __syncthreads();
    }
    #pragma unroll
    for (int i = 0; i < 4; i++)
        #pragma unroll
        for (int n = 0; n < 4; n++)
            outT[(size_t)(bn + tn + n) * 512 + (bi + ti + i)] = __float2half(acc[i][n]);
}

__global__ void bcomb_kernel(const float* __restrict__ b_emb, const float* __restrict__ W1,
                             const float* __restrict__ b1, float* __restrict__ out) {
    int n = blockIdx.x * 256 + threadIdx.x;
    if (n < 1024) {
        float acc = b1[n];
        for (int j = 0; j < 512; j++) acc += b_emb[j] * W1[j * 1024 + n];
        out[n] = acc;
    }
}

// ---------------- weight convert+transpose (3 segments) ----------------
__global__ void conv_w_all(const float* s0, __half* d0,
                           const float* s1, __half* d1,
                           const float* s2, __half* d2) {
    int idx = blockIdx.x * blockDim.x + threadIdx.x;
    const float* src; __half* dst; int K, Nout;
    switch (blockIdx.y) {
        case 0: src = s0; dst = d0; K = 512;  Nout = 1024; break;
        case 1: src = s1; dst = d1; K = 512;  Nout = 512;  break;
        default:src = s2; dst = d2; K = 1024; Nout = 512;  break;
    }
    if (idx < K * Nout) {
        int n = idx / K;
        int k = idx - n * K;
        dst[idx] = __float2half(src[k * Nout + n]);
    }
}

// ---------------- LayerNorm ----------------
__global__ void __launch_bounds__(256)
ln_kernel(const float* __restrict__ x,
          const float* __restrict__ g1, const float* __restrict__ b1, __half* __restrict__ o1,
          const float* __restrict__ g2, const float* __restrict__ b2, __half* __restrict__ o2) {
    int tid = threadIdx.x;
    int g   = tid >> 6;
    int l   = tid & 63;
    size_t t = (size_t)blockIdx.x * 4 + g;
    int c = l * 8;

    const float4* px = (const float4*)(x + t * 512 + c);
    float4 v0 = px[0], v1 = px[1];
    float s = v0.x + v0.y + v0.z + v0.w + v1.x + v1.y + v1.z + v1.w;
    float q = v0.x*v0.x + v0.y*v0.y + v0.z*v0.z + v0.w*v0.w
            + v1.x*v1.x + v1.y*v1.y + v1.z*v1.z + v1.w*v1.w;
    #pragma unroll
    for (int o = 16; o; o >>= 1) {
        s += __shfl_xor_sync(0xffffffffu, s, o);
        q += __shfl_xor_sync(0xffffffffu, q, o);
    }
    __shared__ float ss[8], sq[8];
    int w = tid >> 5;
    if ((tid & 31) == 0) { ss[w] = s; sq[w] = q; }
    __syncthreads();
    s = ss[g * 2] + ss[g * 2 + 1];
    q = sq[g * 2] + sq[g * 2 + 1];
    float mean = s * (1.0f / 512.0f);
    float var  = q * (1.0f / 512.0f) - mean * mean;
    float rstd = rsqrtf(var + 1e-5f);

    float xh[8];
    xh[0]=(v0.x-mean)*rstd; xh[1]=(v0.y-mean)*rstd; xh[2]=(v0.z-mean)*rstd; xh[3]=(v0.w-mean)*rstd;
    xh[4]=(v1.x-mean)*rstd; xh[5]=(v1.y-mean)*rstd; xh[6]=(v1.z-mean)*rstd; xh[7]=(v1.w-mean)*rstd;

    {
        const float4 ga = *(const float4*)(g1 + c), gb = *(const float4*)(g1 + c + 4);
        const float4 ba = *(const float4*)(b1 + c), bb = *(const float4*)(b1 + c + 4);
        uint4 pk;
        pk.x = h2u(xh[0]*ga.x + ba.x, xh[1]*ga.y + ba.y);
        pk.y = h2u(xh[2]*ga.z + ba.z, xh[3]*ga.w + ba.w);
        pk.z = h2u(xh[4]*gb.x + bb.x, xh[5]*gb.y + bb.y);
        pk.w = h2u(xh[6]*gb.z + bb.z, xh[7]*gb.w + bb.w);
        *(uint4*)(o1 + t * 512 + c) = pk;
    }
    if (o2) {
        const float4 ga = *(const float4*)(g2 + c), gb = *(const float4*)(g2 + c + 4);
        const float4 ba = *(const float4*)(b2 + c), bb = *(const float4*)(b2 + c + 4);
        uint4 pk;
        pk.x = h2u(xh[0]*ga.x + ba.x, xh[1]*ga.y + ba.y);
        pk.y = h2u(xh[2]*ga.z + ba.z, xh[3]*ga.w + ba.w);
        pk.z = h2u(xh[4]*gb.x + bb.x, xh[5]*gb.y + bb.y);
        pk.w = h2u(xh[6]*gb.z + bb.z, xh[7]*gb.w + bb.w);
        *(uint4*)(o2 + t * 512 + c) = pk;
    }
}

// ---------------- WMMA GEMM, fp16 acc, BK=64, 3-stage prefetch (round-13 proven) ----------------
enum { EPI_BIAS_F16 = 0, EPI_GELU_F16 = 1, EPI_RESID_F32 = 2 };

#define BM2 128
#define BN2 128
#define BK2 64
#define LDT 72
#define TILE_B (BM2 * LDT * 2)
#define STAGE_B (2 * TILE_B)
#define LDC2 136
#define GEMM_SMEM (3 * STAGE_B)   // 110592 B

template<int K, int EPI>
__global__ void __launch_bounds__(256)
gemm2(const __half* __restrict__ A,
      const __half* __restrict__ Bt,
      const float* __restrict__ bias,
      __half* __restrict__ outH,
      float* __restrict__ outF,
      const float* __restrict__ resid,
      const float* __restrict__ scale,
      int Nout) {
    extern __shared__ __align__(16) unsigned char dsm[];
    __half* sC = (__half*)dsm;

    int tid  = threadIdx.x;
    int warp = tid >> 5;
    int wm = warp & 3;
    int wn = warp >> 2;
    int mbase = blockIdx.y * BM2;
    int nbase = blockIdx.x * BN2;

    int r0c[4], c0c[4];
    #pragma unroll
    for (int it = 0; it < 4; it++) {
        int ch = tid + it * 256;
        r0c[it] = ch >> 3;
        c0c[it] = (ch & 7) << 3;
    }

    wmma::fragment<wmma::accumulator, 16, 16, 16, __half> acc[2][4];
    #pragma unroll
    for (int i = 0; i < 2; i++)
        #pragma unroll
        for (int j = 0; j < 4; j++)
            wmma::fill_fragment(acc[i][j], __float2half(0.0f));

    constexpr int KT = K / BK2;

    auto load_stage = [&](int kt, int st) {
        __half* sA = (__half*)(dsm + st * STAGE_B);
        __half* sB = (__half*)(dsm + st * STAGE_B + TILE_B);
        #pragma unroll
        for (int it = 0; it < 4; it++)
            cp16(sA + r0c[it] * LDT + c0c[it],
                 A + (size_t)(mbase + r0c[it]) * K + kt * BK2 + c0c[it]);
        #pragma unroll
        for (int it = 0; it < 4; it++)
            cp16(sB + r0c[it] * LDT + c0c[it],
                 Bt + (size_t)(nbase + r0c[it]) * K + kt * BK2 + c0c[it]);
    };

    #pragma unroll
    for (int p = 0; p < 3; p++) { load_stage(p, p); cp_commit(); }

    for (int kt = 0; kt < KT; kt++) {
        if (kt + 2 < KT)      cp_wait<2>();
        else if (kt + 1 < KT) cp_wait<1>();
        else                  cp_wait<0>();
        __syncthreads();
        int b = kt % 3;
        __half* sA = (__half*)(dsm + b * STAGE_B);
        __half* sB = (__half*)(dsm + b * STAGE_B + TILE_B);
        #pragma unroll
        for (int ks = 0; ks < BK2; ks += 16) {
            wmma::fragment<wmma::matrix_a, 16, 16, 16, __half, wmma::row_major> af[2];
            wmma::fragment<wmma::matrix_b, 16, 16, 16, __half, wmma::col_major> bf[4];
            wmma::load_matrix_sync(af[0], sA + (wm * 32)      * LDT + ks, LDT);
            wmma::load_matrix_sync(af[1], sA + (wm * 32 + 16) * LDT + ks, LDT);
            #pragma unroll
            for (int j = 0; j < 4; j++)
                wmma::load_matrix_sync(bf[j], sB + (wn * 64 + j * 16) * LDT + ks, LDT);
            #pragma unroll
            for (int i = 0; i < 2; i++)
                #pragma unroll
                for (int j = 0; j < 4; j++)
                    wmma::mma_sync(acc[i][j], af[i], bf[j], acc[i][j]);
        }
        __syncthreads();
        if (kt + 3 < KT) {
            load_stage(kt + 3, b);
            cp_commit();
        }
    }

    #pragma unroll
    for (int i = 0; i < 2; i++)
        #pragma unroll
        for (int j = 0; j < 4; j++)
            wmma::store_matrix_sync(sC + (wm * 32 + i * 16) * LDC2 + wn * 64 + j * 16,
                                    acc[i][j], LDC2, wmma::mem_row_major);
    __syncthreads();

    #pragma unroll 4
    for (int e = tid; e < BM2 * BN2; e += 256) {
        int r = e >> 7;
        int c = e & 127;
        float v = __half2float(sC[r * LDC2 + c]);
        int gr = mbase + r;
        int gc = nbase + c;
        float bz = bias[gc];
        if (EPI == EPI_BIAS_F16) {
            outH[(size_t)gr * Nout + gc] = __float2half(v + bz);
        } else if (EPI == EPI_GELU_F16) {
            float t = v + bz;
            float u = 0.7978845608028654f * (t + 0.044715f * t * t * t);
            float th;
            asm("tanh.approx.f32 %0, %1;" : "=f"(th) : "f"(u));
            outH[(size_t)gr * Nout + gc] = __float2half(0.5f * t * (1.0f + th));
        } else {
            float t = v + bz;
            outF[(size_t)gr * Nout + gc] = resid[(size_t)gr * Nout + gc] + scale[gc] * t;
        }
    }
}

// ---------------- attention: ONLINE softmax over two 96-col halves, 56 KB swizzled smem ----------------
#define ATTN3_SMEM ((64 + 192 + 192) * 64 * 2)   // 57344 bytes

__global__ void __launch_bounds__(128)
attn3_kernel(const __half* __restrict__ q,
             const __half* __restrict__ kv,
             __half* __restrict__ attn_out) {
    extern __shared__ __align__(16) unsigned char dsm[];
    __half* sQ = (__half*)dsm;
    __half* sK = sQ + 64 * 64;
    __half* sV = sK + NKV * 64;

    int bid  = blockIdx.x;
    int head = bid & 7;
    int win  = bid >> 3;
    int g8   = win >> 7;
    int sw   = win & 127;
    size_t tbase = (size_t)g8 * SPER + (size_t)sw * NWIN;

    int tid  = threadIdx.x;
    bool valid0 = (sw > 0);
    bool valid2 = (sw < SWIN - 1);
    int cl0 = valid0 ? (sw - 1) : 0;
    int cl2 = valid2 ? (sw + 1) : (SWIN - 1);
    size_t kb0 = (size_t)g8 * SPER + (size_t)cl0 * NWIN;
    size_t kb2 = (size_t)g8 * SPER + (size_t)cl2 * NWIN;

    // group 0: Q + K (swizzled)
    #pragma unroll
    for (int it = 0; it < 4; it++) {
        int ch = tid + it * 128;
        int r = ch >> 3, cc = (ch & 7) << 3;
        cp16(sQ + swz(r, cc), q + (tbase + r) * 512 + head * 64 + cc);
    }
    #pragma unroll
    for (int it = 0; it < 12; it++) {
        int ch = tid + it * 128;
        int r = ch >> 3, cc = (ch & 7) << 3;
        int nb = r >> 6, lr2 = r & 63;
        size_t tok = (nb == 0 ? kb0 : (nb == 1 ? tbase : kb2)) + lr2;
        cp16(sK + swz(r, cc), kv + tok * 1024 + head * 64 + cc);
    }
    cp_commit();
    // group 1: V
    #pragma unroll
    for (int it = 0; it < 12; it++) {
        int ch = tid + it * 128;
        int r = ch >> 3, cc = (ch & 7) << 3;
        int nb = r >> 6, lr2 = r & 63;
        size_t tok = (nb == 0 ? kb0 : (nb == 1 ? tbase : kb2)) + lr2;
        cp16(sV + swz(r, cc), kv + tok * 1024 + 512 + head * 64 + cc);
    }
    cp_commit();

    cp_wait<1>();     // Q + K resident
    __syncthreads();

    int warp = tid >> 5;
    int lane = tid & 31;
    int g    = lane >> 2;
    int tig  = lane & 3;
    int lr   = lane & 7;
    int lm   = lane >> 3;
    int r0   = warp * 16;

    uint32_t aq[4][4];
    #pragma unroll
    for (int kk = 0; kk < 4; kk++) {
        int row = r0 + lr + ((lm & 1) << 3);
        int col = kk * 16 + ((lm & 2) << 2);
        ldsm4(aq[kk][0], aq[kk][1], aq[kk][2], aq[kk][3], smem_u32(sQ + swz(row, col)));
    }

    int lo = valid0 ? 0   : 64;
    int hi = valid2 ? 192 : 128;

    float m0 = -3.0e38f, m1 = -3.0e38f;
    float s0 = 0.f, s1 = 0.f;
    float oa[8][4];
    #pragma unroll
    for (int j = 0; j < 8; j++) { oa[j][0]=0.f; oa[j][1]=0.f; oa[j][2]=0.f; oa[j][3]=0.f; }

    #pragma unroll
    for (int h = 0; h < 2; h++) {
        // S-half = Q @ K[h*96 : h*96+96]^T : 12 frags
        float sc[12][4];
        #pragma unroll
        for (int j = 0; j < 12; j++) { sc[j][0]=0.f; sc[j][1]=0.f; sc[j][2]=0.f; sc[j][3]=0.f; }
        #pragma unroll
        for (int nb = 0; nb < 6; nb++) {
            #pragma unroll
            for (int kk = 0; kk < 4; kk++) {
                int row = h * 96 + nb * 16 + lr + ((lm & 2) << 2);
                int col = kk * 16 + ((lm & 1) << 3);
                uint32_t b4[4];
                ldsm4(b4[0], b4[1], b4[2], b4[3], smem_u32(sK + swz(row, col)));
                hmma(sc[2 * nb],     aq[kk], &b4[0]);
                hmma(sc[2 * nb + 1], aq[kk], &b4[2]);
            }
        }

        // masked local max
        float lx0 = -3.0e38f, lx1 = -3.0e38f;
        #pragma unroll
        for (int j = 0; j < 12; j++) {
            int c0 = h * 96 + j * 8 + 2 * tig;
            if (c0 >= lo && c0 < hi) {
                lx0 = fmaxf(lx0, fmaxf(sc[j][0], sc[j][1]));
                lx1 = fmaxf(lx1, fmaxf(sc[j][2], sc[j][3]));
            }
        }
        lx0 = fmaxf(lx0, __shfl_xor_sync(0xffffffffu, lx0, 1));
        lx0 = fmaxf(lx0, __shfl_xor_sync(0xffffffffu, lx0, 2));
        lx1 = fmaxf(lx1, __shfl_xor_sync(0xffffffffu, lx1, 1));
        lx1 = fmaxf(lx1, __shfl_xor_sync(0xffffffffu, lx1, 2));

        float mn0 = fmaxf(m0, lx0);
        float mn1 = fmaxf(m1, lx1);
        float cr0 = __expf((m0 - mn0) * 0.125f);   // first pass: exp(-huge)=0
        float cr1 = __expf((m1 - mn1) * 0.125f);
        m0 = mn0; m1 = mn1;

        float ls0 = 0.f, ls1 = 0.f;
        #pragma unroll
        for (int j = 0; j < 12; j++) {
            int c0 = h * 96 + j * 8 + 2 * tig;
            bool ok = (c0 >= lo) && (c0 < hi);
            float e0 = ok ? __expf((sc[j][0] - m0) * 0.125f) : 0.f;
            float e1 = ok ? __expf((sc[j][1] - m0) * 0.125f) : 0.f;
            float e2 = ok ? __expf((sc[j][2] - m1) * 0.125f) : 0.f;
            float e3 = ok ? __expf((sc[j][3] - m1) * 0.125f) : 0.f;
            sc[j][0] = e0; sc[j][1] = e1; sc[j][2] = e2; sc[j][3] = e3;
            ls0 += e0 + e1;
            ls1 += e2 + e3;
        }
        ls0 += __shfl_xor_sync(0xffffffffu, ls0, 1);
        ls0 += __shfl_xor_sync(0xffffffffu, ls0, 2);
        ls1 += __shfl_xor_sync(0xffffffffu, ls1, 1);
        ls1 += __shfl_xor_sync(0xffffffffu, ls1, 2);
        s0 = s0 * cr0 + ls0;
        s1 = s1 * cr1 + ls1;

        #pragma unroll
        for (int j = 0; j < 8; j++) {
            oa[j][0] *= cr0; oa[j][1] *= cr0;
            oa[j][2] *= cr1; oa[j][3] *= cr1;
        }

        if (h == 0) {       // V resident before first P@V
            cp_wait<0>();
            __syncthreads();
        }

        // oa += P_half @ V_half
        #pragma unroll
        for (int kk2 = 0; kk2 < 6; kk2++) {
            uint32_t ap[4];
            ap[0] = h2u(sc[2*kk2][0],   sc[2*kk2][1]);
            ap[1] = h2u(sc[2*kk2][2],   sc[2*kk2][3]);
            ap[2] = h2u(sc[2*kk2+1][0], sc[2*kk2+1][1]);
            ap[3] = h2u(sc[2*kk2+1][2], sc[2*kk2+1][3]);
            #pragma unroll
            for (int nb2 = 0; nb2 < 4; nb2++) {
                int row = h * 96 + kk2 * 16 + lr + ((lm & 1) << 3);
                int col = nb2 * 16 + ((lm & 2) << 2);
                uint32_t b4[4];
                ldsm4t(b4[0], b4[1], b4[2], b4[3], smem_u32(sV + swz(row, col)));
                hmma(oa[2 * nb2],     ap, &b4[0]);
                hmma(oa[2 * nb2 + 1], ap, &b4[2]);
            }
        }
    }

    float inv0 = 1.0f / s0;
    float inv1 = 1.0f / s1;

    size_t rowg = tbase + r0 + g;
    #pragma unroll
    for (int j2 = 0; j2 < 8; j2++) {
        *(uint32_t*)(attn_out + rowg * 512 + head * 64 + j2 * 8 + 2 * tig) =
            h2u(oa[j2][0] * inv0, oa[j2][1] * inv0);
        *(uint32_t*)(attn_out + (rowg + 8) * 512 + head * 64 + j2 * 8 + 2 * tig) =
            h2u(oa[j2][2] * inv1, oa[j2][3] * inv1);
    }
}

// ---------------- host launcher ----------------
extern "C" void kernel_launch(void* const* d_in, const int* in_sizes, int n_in,
                              void* d_out, int out_size) {
    (void)in_sizes; (void)n_in; (void)out_size;
    const float* x       = (const float*)d_in[0];
    const float* ln_q_g  = (const float*)d_in[1];
    const float* ln_q_b  = (const float*)d_in[2];
    const float* ln_kv_g = (const float*)d_in[3];
    const float* ln_kv_b = (const float*)d_in[4];
    const float* W_kv    = (const float*)d_in[5];
    const float* b_kv    = (const float*)d_in[6];
    const float* W_o     = (const float*)d_in[7];
    const float* b_o     = (const float*)d_in[8];
    const float* gamma   = (const float*)d_in[9];
    const float* ln_m_g  = (const float*)d_in[10];
    const float* ln_m_b  = (const float*)d_in[11];
    const float* W_emb   = (const float*)d_in[12];
    const float* b_emb   = (const float*)d_in[13];
    const float* W1      = (const float*)d_in[14];
    const float* b1      = (const float*)d_in[15];
    const float* W2      = (const float*)d_in[16];
    const float* b2      = (const float*)d_in[17];
    const float* gamma_mlp = (const float*)d_in[18];
    float* out = (float*)d_out;

    void *p_q, *p_akv, *p_kv, *p_attn, *p_x1, *p_h1;
    void *p_wkv, *p_wo, *p_w1c, *p_w2, *p_bc;
    cudaGetSymbolAddress(&p_q,    g_q);
    cudaGetSymbolAddress(&p_akv,  g_akv);
    cudaGetSymbolAddress(&p_kv,   g_kv);
    cudaGetSymbolAddress(&p_attn, g_attn);
    cudaGetSymbolAddress(&p_x1,   g_x1);
    cudaGetSymbolAddress(&p_h1,   g_h1);
    cudaGetSymbolAddress(&p_wkv,  g_wkv);
    cudaGetSymbolAddress(&p_wo,   g_wo);
    cudaGetSymbolAddress(&p_w1c,  g_w1c);
    cudaGetSymbolAddress(&p_w2,   g_w2);
    cudaGetSymbolAddress(&p_bc,   g_bcomb);

    cudaFuncSetAttribute(attn3_kernel, cudaFuncAttributeMaxDynamicSharedMemorySize, ATTN3_SMEM);
    cudaFuncSetAttribute(gemm2<512,  EPI_BIAS_F16>,  cudaFuncAttributeMaxDynamicSharedMemorySize, GEMM_SMEM);
    cudaFuncSetAttribute(gemm2<512,  EPI_GELU_F16>,  cudaFuncAttributeMaxDynamicSharedMemorySize, GEMM_SMEM);
    cudaFuncSetAttribute(gemm2<512,  EPI_RESID_F32>, cudaFuncAttributeMaxDynamicSharedMemorySize, GEMM_SMEM);
    cudaFuncSetAttribute(gemm2<1024, EPI_RESID_F32>, cudaFuncAttributeMaxDynamicSharedMemorySize, GEMM_SMEM);

    // 0a) W_comb (fp16 transposed) + b_comb
    wcomb_kernel<<<dim3(16, 8), 256>>>(W_emb, W1, (__half*)p_w1c);
    bcomb_kernel<<<4, 256>>>(b_emb, W1, b1, (float*)p_bc);

    // 0b) weight convert+transpose -> fp16
    conv_w_all<<<dim3(2048, 3), 256>>>(W_kv, (__half*)p_wkv,
                                       W_o,  (__half*)p_wo,
                                       W2,   (__half*)p_w2);

    // 1) dual LN
    ln_kernel<<<NTOKS / 4, 256>>>(x, ln_q_g, ln_q_b, (__half*)p_q,
                                     ln_kv_g, ln_kv_b, (__half*)p_akv);

    // 2) kv = akv @ W_kv + b_kv
    gemm2<512, EPI_BIAS_F16><<<dim3(1024 / BN2, NTOKS / BM2), 256, GEMM_SMEM>>>(
        (const __half*)p_akv, (const __half*)p_wkv, b_kv,
        (__half*)p_kv, nullptr, nullptr, nullptr, 1024);

    // 3) windowed attention (online softmax)
    attn3_kernel<<<NGROUPS * SWIN * HEADS, 128, ATTN3_SMEM>>>(
        (const __half*)p_q, (const __half*)p_kv, (__half*)p_attn);

    // 4) x1 = x + gamma * (attn @ W_o + b_o)
    gemm2<512, EPI_RESID_F32><<<dim3(512 / BN2, NTOKS / BM2), 256, GEMM_SMEM>>>(
        (const __half*)p_attn, (const __half*)p_wo, b_o,
        nullptr, (float*)p_x1, x, gamma, 512);

    // 5) aemb = LN_m(x1)
    ln_kernel<<<NTOKS / 4, 256>>>((const float*)p_x1, ln_m_g, ln_m_b, (__half*)p_akv,
                                  nullptr, nullptr, nullptr);

    // 6) h1 = gelu(aemb @ W_comb + b_comb)
    gemm2<512, EPI_GELU_F16><<<dim3(1024 / BN2, NTOKS / BM2), 256, GEMM_SMEM>>>(
        (const __half*)p_akv, (const __half*)p_w1c, (const float*)p_bc,
        (__half*)p_h1, nullptr, nullptr, nullptr, 1024);

    // 7) out = x1 + gamma_mlp * (h1 @ W2 + b2)
    gemm2<1024, EPI_RESID_F32><<<dim3(512 / BN2, NTOKS / BM2), 256, GEMM_SMEM>>>(
        (const __half*)p_h1, (const __half*)p_w2, b2,
        nullptr, out, (const float*)p_x1, gamma_mlp, 512);
}

// round 15
// speedup vs baseline: 1.0174x; 1.0174x over previous
#include <cuda_runtime.h>
#include <cuda_fp16.h>
#include <mma.h>
#include <math.h>
#include <stdint.h>

using namespace nvcuda;

// Problem constants
#define NTOKS   65536
#define NGROUPS 8
#define SPER    8192
#define SWIN    128
#define NWIN    64
#define NKV     192
#define HEADS   8

// ---------------- device scratch ----------------
__device__ __align__(1024) __half g_q   [(size_t)NTOKS * 512];
__device__ __align__(1024) __half g_akv [(size_t)NTOKS * 512];
__device__ __align__(1024) __half g_kv  [(size_t)NTOKS * 1024];
__device__ __align__(1024) __half g_attn[(size_t)NTOKS * 512];
__device__ __align__(1024) float  g_x1  [(size_t)NTOKS * 512];
__device__ __align__(1024) __half g_h1  [(size_t)NTOKS * 1024];
__device__ __align__(1024) __half g_wkv [1024 * 512];
__device__ __align__(1024) __half g_wo  [512 * 512];
__device__ __align__(1024) __half g_w1c [1024 * 512];
__device__ __align__(1024) __half g_w2  [512 * 1024];
__device__ float g_bcomb[1024];

// ---------------- helpers ----------------
__device__ __forceinline__ uint32_t smem_u32(const void* p) {
    uint32_t a;
    asm("{ .reg .u64 t; cvta.to.shared.u64 t, %1; cvt.u32.u64 %0, t; }" : "=r"(a) : "l"(p));
    return a;
}
__device__ __forceinline__ void cp16_s(uint32_t daddr, const void* src) {
    asm volatile("cp.async.cg.shared.global [%0], [%1], 16;\n" :: "r"(daddr), "l"(src));
}
__device__ __forceinline__ void cp16(void* dst, const void* src) { cp16_s(smem_u32(dst), src); }
__device__ __forceinline__ void cp_commit() { asm volatile("cp.async.commit_group;\n"); }
template<int N> __device__ __forceinline__ void cp_wait() {
    asm volatile("cp.async.wait_group %0;\n" :: "n"(N));
}
__device__ __forceinline__ void ldsm4(uint32_t& r0, uint32_t& r1, uint32_t& r2, uint32_t& r3,
                                      uint32_t addr) {
    asm volatile("ldmatrix.sync.aligned.m8n8.x4.shared.b16 {%0,%1,%2,%3}, [%4];"
                 : "=r"(r0), "=r"(r1), "=r"(r2), "=r"(r3) : "r"(addr));
}
__device__ __forceinline__ void ldsm4t(uint32_t& r0, uint32_t& r1, uint32_t& r2, uint32_t& r3,
                                       uint32_t addr) {
    asm volatile("ldmatrix.sync.aligned.m8n8.x4.trans.shared.b16 {%0,%1,%2,%3}, [%4];"
                 : "=r"(r0), "=r"(r1), "=r"(r2), "=r"(r3) : "r"(addr));
}
__device__ __forceinline__ void hmma(float* d, const uint32_t* a, const uint32_t* b) {
    asm volatile("mma.sync.aligned.m16n8k16.row.col.f32.f16.f16.f32 "
                 "{%0,%1,%2,%3},{%4,%5,%6,%7},{%8,%9},{%0,%1,%2,%3};"
                 : "+f"(d[0]), "+f"(d[1]), "+f"(d[2]), "+f"(d[3])
                 : "r"(a[0]), "r"(a[1]), "r"(a[2]), "r"(a[3]), "r"(b[0]), "r"(b[1]));
}
__device__ __forceinline__ uint32_t h2u(float a, float b) {
    __half2 t = __floats2half2_rn(a, b);
    return *(uint32_t*)&t;
}

// ---------------- W_comb = W_emb @ W1, fp16 transposed ----------------
__global__ void __launch_bounds__(256)
wcomb_kernel(const float* __restrict__ We, const float* __restrict__ W1, __half* __restrict__ outT) {
    __shared__ float sa[64][65];
    __shared__ float sb[64][65];
    int bi = blockIdx.y * 64, bn = blockIdx.x * 64;
    int tid = threadIdx.x;
    int ti = (tid >> 4) * 4, tn = (tid & 15) * 4;
    float acc[4][4] = {};
    for (int j0 = 0; j0 < 512; j0 += 64) {
        for (int t = tid; t < 4096; t += 256) {
            int r = t >> 6, c = t & 63;
            sa[r][c] = We[(size_t)(bi + r) * 512 + j0 + c];
            sb[r][c] = W1[(size_t)(j0 + r) * 1024 + bn + c];
        }
        __syncthreads();
        for (int j = 0; j < 64; j++) {
            float b0 = sb[j][tn], b1 = sb[j][tn + 1], b2 = sb[j][tn + 2], b3 = sb[j][tn + 3];
            #pragma unroll
            for (int i = 0; i < 4; i++) {
                float av = sa[ti + i][j];
                acc[i][0] += av * b0; acc[i][1] += av * b1;
                acc[i][2] += av * b2; acc[i][3] += av * b3;
            }
        }
        __syncthreads();
    }
    #pragma unroll
    for (int i = 0; i < 4; i++)
        #pragma unroll
        for (int n = 0; n < 4; n++)
            outT[(size_t)(bn + tn + n) * 512 + (bi + ti + i)] = __float2half(acc[i][n]);
}

__global__ void bcomb_kernel(const float* __restrict__ b_emb, const float* __restrict__ W1,
                             const float* __restrict__ b1, float* __restrict__ out) {
    int n = blockIdx.x * 256 + threadIdx.x;
    if (n < 1024) {
        float acc = b1[n];
        for (int j = 0; j < 512; j++) acc += b_emb[j] * W1[j * 1024 + n];
        out[n] = acc;
    }
}

// ---------------- weight convert+transpose: smem-tiled, coalesced both sides ----------------
// dst[n][k] = fp16(src[k][n]); 32x32 fp32 tiles. Grid: (K/32, Nout/32, segment)
__global__ void __launch_bounds__(256)
conv_w_all(const float* s0, __half* d0,   // W_kv 512x1024
           const float* s1, __half* d1,   // W_o  512x512
           const float* s2, __half* d2) { // W2  1024x512
    const float* src; __half* dst; int K, Nout;
    switch (blockIdx.z) {
        case 0: src = s0; dst = d0; K = 512;  Nout = 1024; break;
        case 1: src = s1; dst = d1; K = 512;  Nout = 512;  break;
        default:src = s2; dst = d2; K = 1024; Nout = 512;  break;
    }
    int k0 = blockIdx.x * 32;
    int n0 = blockIdx.y * 32;
    if (k0 >= K || n0 >= Nout) return;

    __shared__ float tile[32][33];
    int tx = threadIdx.x & 31;       // column within row (coalesced)
    int ty = threadIdx.x >> 5;       // 8 rows per pass
    #pragma unroll
    for (int r = 0; r < 32; r += 8)
        tile[ty + r][tx] = src[(size_t)(k0 + ty + r) * Nout + n0 + tx];
    __syncthreads();
    // write: row = n, col = k (coalesced along k)
    #pragma unroll
    for (int r = 0; r < 32; r += 8)
        dst[(size_t)(n0 + ty + r) * K + k0 + tx] = __float2half(tile[tx][ty + r]);
}

// ---------------- LayerNorm ----------------
__global__ void __launch_bounds__(256)
ln_kernel(const float* __restrict__ x,
          const float* __restrict__ g1, const float* __restrict__ b1, __half* __restrict__ o1,
          const float* __restrict__ g2, const float* __restrict__ b2, __half* __restrict__ o2) {
    int tid = threadIdx.x;
    int g   = tid >> 6;
    int l   = tid & 63;
    size_t t = (size_t)blockIdx.x * 4 + g;
    int c = l * 8;

    const float4* px = (const float4*)(x + t * 512 + c);
    float4 v0 = px[0], v1 = px[1];
    float s = v0.x + v0.y + v0.z + v0.w + v1.x + v1.y + v1.z + v1.w;
    float q = v0.x*v0.x + v0.y*v0.y + v0.z*v0.z + v0.w*v0.w
            + v1.x*v1.x + v1.y*v1.y + v1.z*v1.z + v1.w*v1.w;
    #pragma unroll
    for (int o = 16; o; o >>= 1) {
        s += __shfl_xor_sync(0xffffffffu, s, o);
        q += __shfl_xor_sync(0xffffffffu, q, o);
    }
    __shared__ float ss[8], sq[8];
    int w = tid >> 5;
    if ((tid & 31) == 0) { ss[w] = s; sq[w] = q; }
    __syncthreads();
    s = ss[g * 2] + ss[g * 2 + 1];
    q = sq[g * 2] + sq[g * 2 + 1];
    float mean = s * (1.0f / 512.0f);
    float var  = q * (1.0f / 512.0f) - mean * mean;
    float rstd = rsqrtf(var + 1e-5f);

    float xh[8];
    xh[0]=(v0.x-mean)*rstd; xh[1]=(v0.y-mean)*rstd; xh[2]=(v0.z-mean)*rstd; xh[3]=(v0.w-mean)*rstd;
    xh[4]=(v1.x-mean)*rstd; xh[5]=(v1.y-mean)*rstd; xh[6]=(v1.z-mean)*rstd; xh[7]=(v1.w-mean)*rstd;

    {
        const float4 ga = *(const float4*)(g1 + c), gb = *(const float4*)(g1 + c + 4);
        const float4 ba = *(const float4*)(b1 + c), bb = *(const float4*)(b1 + c + 4);
        uint4 pk;
        pk.x = h2u(xh[0]*ga.x + ba.x, xh[1]*ga.y + ba.y);
        pk.y = h2u(xh[2]*ga.z + ba.z, xh[3]*ga.w + ba.w);
        pk.z = h2u(xh[4]*gb.x + bb.x, xh[5]*gb.y + bb.y);
        pk.w = h2u(xh[6]*gb.z + bb.z, xh[7]*gb.w + bb.w);
        *(uint4*)(o1 + t * 512 + c) = pk;
    }
    if (o2) {
        const float4 ga = *(const float4*)(g2 + c), gb = *(const float4*)(g2 + c + 4);
        const float4 ba = *(const float4*)(b2 + c), bb = *(const float4*)(b2 + c + 4);
        uint4 pk;
        pk.x = h2u(xh[0]*ga.x + ba.x, xh[1]*ga.y + ba.y);
        pk.y = h2u(xh[2]*ga.z + ba.z, xh[3]*ga.w + ba.w);
        pk.z = h2u(xh[4]*gb.x + bb.x, xh[5]*gb.y + bb.y);
        pk.w = h2u(xh[6]*gb.z + bb.z, xh[7]*gb.w + bb.w);
        *(uint4*)(o2 + t * 512 + c) = pk;
    }
}

// ---------------- WMMA GEMM, fp16 acc, BK=64, 3-stage prefetch (round-13 proven) ----------------
enum { EPI_BIAS_F16 = 0, EPI_GELU_F16 = 1, EPI_RESID_F32 = 2 };

#define BM2 128
#define BN2 128
#define BK2 64
#define LDT 72
#define TILE_B (BM2 * LDT * 2)
#define STAGE_B (2 * TILE_B)
#define LDC2 136
#define GEMM_SMEM (3 * STAGE_B)   // 110592 B

template<int K, int EPI>
__global__ void __launch_bounds__(256)
gemm2(const __half* __restrict__ A,
      const __half* __restrict__ Bt,
      const float* __restrict__ bias,
      __half* __restrict__ outH,
      float* __restrict__ outF,
      const float* __restrict__ resid,
      const float* __restrict__ scale,
      int Nout) {
    extern __shared__ __align__(16) unsigned char dsm[];
    __half* sC = (__half*)dsm;

    int tid  = threadIdx.x;
    int warp = tid >> 5;
    int wm = warp & 3;
    int wn = warp >> 2;
    int mbase = blockIdx.y * BM2;
    int nbase = blockIdx.x * BN2;

    int r0c[4], c0c[4];
    #pragma unroll
    for (int it = 0; it < 4; it++) {
        int ch = tid + it * 256;
        r0c[it] = ch >> 3;
        c0c[it] = (ch & 7) << 3;
    }

    wmma::fragment<wmma::accumulator, 16, 16, 16, __half> acc[2][4];
    #pragma unroll
    for (int i = 0; i < 2; i++)
        #pragma unroll
        for (int j = 0; j < 4; j++)
            wmma::fill_fragment(acc[i][j], __float2half(0.0f));

    constexpr int KT = K / BK2;

    auto load_stage = [&](int kt, int st) {
        __half* sA = (__half*)(dsm + st * STAGE_B);
        __half* sB = (__half*)(dsm + st * STAGE_B + TILE_B);
        #pragma unroll
        for (int it = 0; it < 4; it++)
            cp16(sA + r0c[it] * LDT + c0c[it],
                 A + (size_t)(mbase + r0c[it]) * K + kt * BK2 + c0c[it]);
        #pragma unroll
        for (int it = 0; it < 4; it++)
            cp16(sB + r0c[it] * LDT + c0c[it],
                 Bt + (size_t)(nbase + r0c[it]) * K + kt * BK2 + c0c[it]);
    };

    #pragma unroll
    for (int p = 0; p < 3; p++) { load_stage(p, p); cp_commit(); }

    for (int kt = 0; kt < KT; kt++) {
        if (kt + 2 < KT)      cp_wait<2>();
        else if (kt + 1 < KT) cp_wait<1>();
        else                  cp_wait<0>();
        __syncthreads();
        int b = kt % 3;
        __half* sA = (__half*)(dsm + b * STAGE_B);
        __half* sB = (__half*)(dsm + b * STAGE_B + TILE_B);
        #pragma unroll
        for (int ks = 0; ks < BK2; ks += 16) {
            wmma::fragment<wmma::matrix_a, 16, 16, 16, __half, wmma::row_major> af[2];
            wmma::fragment<wmma::matrix_b, 16, 16, 16, __half, wmma::col_major> bf[4];
            wmma::load_matrix_sync(af[0], sA + (wm * 32)      * LDT + ks, LDT);
            wmma::load_matrix_sync(af[1], sA + (wm * 32 + 16) * LDT + ks, LDT);
            #pragma unroll
            for (int j = 0; j < 4; j++)
                wmma::load_matrix_sync(bf[j], sB + (wn * 64 + j * 16) * LDT + ks, LDT);
            #pragma unroll
            for (int i = 0; i < 2; i++)
                #pragma unroll
                for (int j = 0; j < 4; j++)
                    wmma::mma_sync(acc[i][j], af[i], bf[j], acc[i][j]);
        }
        __syncthreads();
        if (kt + 3 < KT) {
            load_stage(kt + 3, b);
            cp_commit();
        }
    }

    #pragma unroll
    for (int i = 0; i < 2; i++)
        #pragma unroll
        for (int j = 0; j < 4; j++)
            wmma::store_matrix_sync(sC + (wm * 32 + i * 16) * LDC2 + wn * 64 + j * 16,
                                    acc[i][j], LDC2, wmma::mem_row_major);
    __syncthreads();

    #pragma unroll 4
    for (int e = tid; e < BM2 * BN2; e += 256) {
        int r = e >> 7;
        int c = e & 127;
        float v = __half2float(sC[r * LDC2 + c]);
        int gr = mbase + r;
        int gc = nbase + c;
        float bz = bias[gc];
        if (EPI == EPI_BIAS_F16) {
            outH[(size_t)gr * Nout + gc] = __float2half(v + bz);
        } else if (EPI == EPI_GELU_F16) {
            float t = v + bz;
            float u = 0.7978845608028654f * (t + 0.044715f * t * t * t);
            float th;
            asm("tanh.approx.f32 %0, %1;" : "=f"(th) : "f"(u));
            outH[(size_t)gr * Nout + gc] = __float2half(0.5f * t * (1.0f + th));
        } else {
            float t = v + bz;
            outF[(size_t)gr * Nout + gc] = resid[(size_t)gr * Nout + gc] + scale[gc] * t;
        }
    }
}

// ---------------- attention: register softmax, V overlapped (round-13 proven) ----------------
#define LDQ 72
#define ATTN2_SMEM ((64 + 192 + 192) * LDQ * 2)   // 64512 bytes

__global__ void __launch_bounds__(128)
attn2_kernel(const __half* __restrict__ q,
             const __half* __restrict__ kv,
             __half* __restrict__ attn_out) {
    extern __shared__ __align__(16) unsigned char dsm[];
    __half* sQ = (__half*)dsm;
    __half* sK = sQ + 64 * LDQ;
    __half* sV = sK + NKV * LDQ;

    int bid  = blockIdx.x;
    int head = bid & 7;
    int win  = bid >> 3;
    int g8   = win >> 7;
    int sw   = win & 127;
    size_t tbase = (size_t)g8 * SPER + (size_t)sw * NWIN;

    int tid  = threadIdx.x;
    bool valid0 = (sw > 0);
    bool valid2 = (sw < SWIN - 1);
    int cl0 = valid0 ? (sw - 1) : 0;
    int cl2 = valid2 ? (sw + 1) : (SWIN - 1);
    size_t kb0 = (size_t)g8 * SPER + (size_t)cl0 * NWIN;
    size_t kb2 = (size_t)g8 * SPER + (size_t)cl2 * NWIN;

    // group 0: Q + K
    #pragma unroll
    for (int it = 0; it < 4; it++) {
        int ch = tid + it * 128;
        int r = ch >> 3, cc = (ch & 7) << 3;
        cp16(sQ + r * LDQ + cc, q + (tbase + r) * 512 + head * 64 + cc);
    }
    #pragma unroll
    for (int it = 0; it < 12; it++) {
        int ch = tid + it * 128;
        int r = ch >> 3, cc = (ch & 7) << 3;
        int nb = r >> 6, lr2 = r & 63;
        size_t tok = (nb == 0 ? kb0 : (nb == 1 ? tbase : kb2)) + lr2;
        cp16(sK + r * LDQ + cc, kv + tok * 1024 + head * 64 + cc);
    }
    cp_commit();
    // group 1: V
    #pragma unroll
    for (int it = 0; it < 12; it++) {
        int ch = tid + it * 128;
        int r = ch >> 3, cc = (ch & 7) << 3;
        int nb = r >> 6, lr2 = r & 63;
        size_t tok = (nb == 0 ? kb0 : (nb == 1 ? tbase : kb2)) + lr2;
        cp16(sV + r * LDQ + cc, kv + tok * 1024 + 512 + head * 64 + cc);
    }
    cp_commit();

    cp_wait<1>();
    __syncthreads();

    int warp = tid >> 5;
    int lane = tid & 31;
    int g    = lane >> 2;
    int tig  = lane & 3;
    int lr   = lane & 7;
    int lm   = lane >> 3;
    int r0   = warp * 16;

    uint32_t aq[4][4];
    #pragma unroll
    for (int kk = 0; kk < 4; kk++) {
        int row = r0 + lr + ((lm & 1) << 3);
        int col = kk * 16 + ((lm & 2) << 2);
        ldsm4(aq[kk][0], aq[kk][1], aq[kk][2], aq[kk][3], smem_u32(sQ + row * LDQ + col));
    }

    float sc[24][4];
    #pragma unroll
    for (int j = 0; j < 24; j++) { sc[j][0]=0.f; sc[j][1]=0.f; sc[j][2]=0.f; sc[j][3]=0.f; }

    #pragma unroll
    for (int nb = 0; nb < 12; nb++) {
        #pragma unroll
        for (int kk = 0; kk < 4; kk++) {
            int row = nb * 16 + lr + ((lm & 2) << 2);
            int col = kk * 16 + ((lm & 1) << 3);
            uint32_t b4[4];
            ldsm4(b4[0], b4[1], b4[2], b4[3], smem_u32(sK + row * LDQ + col));
            hmma(sc[2 * nb],     aq[kk], &b4[0]);
            hmma(sc[2 * nb + 1], aq[kk], &b4[2]);
        }
    }

    int lo = valid0 ? 0   : 64;
    int hi = valid2 ? 192 : 128;
    float mx0 = -3.0e38f, mx1 = -3.0e38f;
    #pragma unroll
    for (int j = 0; j < 24; j++) {
        int c0 = j * 8 + 2 * tig;
        if (c0 >= lo && c0 < hi) {
            mx0 = fmaxf(mx0, fmaxf(sc[j][0], sc[j][1]));
            mx1 = fmaxf(mx1, fmaxf(sc[j][2], sc[j][3]));
        }
    }
    mx0 = fmaxf(mx0, __shfl_xor_sync(0xffffffffu, mx0, 1));
    mx0 = fmaxf(mx0, __shfl_xor_sync(0xffffffffu, mx0, 2));
    mx1 = fmaxf(mx1, __shfl_xor_sync(0xffffffffu, mx1, 1));
    mx1 = fmaxf(mx1, __shfl_xor_sync(0xffffffffu, mx1, 2));

    float sum0 = 0.f, sum1 = 0.f;
    #pragma unroll
    for (int j = 0; j < 24; j++) {
        int c0 = j * 8 + 2 * tig;
        bool ok = (c0 >= lo) && (c0 < hi);
        float e0 = ok ? __expf((sc[j][0] - mx0) * 0.125f) : 0.f;
        float e1 = ok ? __expf((sc[j][1] - mx0) * 0.125f) : 0.f;
        float e2 = ok ? __expf((sc[j][2] - mx1) * 0.125f) : 0.f;
        float e3 = ok ? __expf((sc[j][3] - mx1) * 0.125f) : 0.f;
        sc[j][0] = e0; sc[j][1] = e1; sc[j][2] = e2; sc[j][3] = e3;
        sum0 += e0 + e1;
        sum1 += e2 + e3;
    }
    sum0 += __shfl_xor_sync(0xffffffffu, sum0, 1);
    sum0 += __shfl_xor_sync(0xffffffffu, sum0, 2);
    sum1 += __shfl_xor_sync(0xffffffffu, sum1, 1);
    sum1 += __shfl_xor_sync(0xffffffffu, sum1, 2);
    float inv0 = 1.0f / sum0;
    float inv1 = 1.0f / sum1;

    cp_wait<0>();
    __syncthreads();

    float oa[8][4];
    #pragma unroll
    for (int j = 0; j < 8; j++) { oa[j][0]=0.f; oa[j][1]=0.f; oa[j][2]=0.f; oa[j][3]=0.f; }

    #pragma unroll
    for (int kk2 = 0; kk2 < 12; kk2++) {
        uint32_t ap[4];
        ap[0] = h2u(sc[2*kk2][0]   * inv0, sc[2*kk2][1]   * inv0);
        ap[1] = h2u(sc[2*kk2][2]   * inv1, sc[2*kk2][3]   * inv1);
        ap[2] = h2u(sc[2*kk2+1][0] * inv0, sc[2*kk2+1][1] * inv0);
        ap[3] = h2u(sc[2*kk2+1][2] * inv1, sc[2*kk2+1][3] * inv1);
        #pragma unroll
        for (int nb2 = 0; nb2 < 4; nb2++) {
            int row = kk2 * 16 + lr + ((lm & 1) << 3);
            int col = nb2 * 16 + ((lm & 2) << 2);
            uint32_t b4[4];
            ldsm4t(b4[0], b4[1], b4[2], b4[3], smem_u32(sV + row * LDQ + col));
            hmma(oa[2 * nb2],     ap, &b4[0]);
            hmma(oa[2 * nb2 + 1], ap, &b4[2]);
        }
    }

    size_t rowg = tbase + r0 + g;
    #pragma unroll
    for (int j2 = 0; j2 < 8; j2++) {
        *(uint32_t*)(attn_out + rowg * 512 + head * 64 + j2 * 8 + 2 * tig) =
            h2u(oa[j2][0], oa[j2][1]);
        *(uint32_t*)(attn_out + (rowg + 8) * 512 + head * 64 + j2 * 8 + 2 * tig) =
            h2u(oa[j2][2], oa[j2][3]);
    }
}

// ---------------- host launcher ----------------
extern "C" void kernel_launch(void* const* d_in, const int* in_sizes, int n_in,
                              void* d_out, int out_size) {
    (void)in_sizes; (void)n_in; (void)out_size;
    const float* x       = (const float*)d_in[0];
    const float* ln_q_g  = (const float*)d_in[1];
    const float* ln_q_b  = (const float*)d_in[2];
    const float* ln_kv_g = (const float*)d_in[3];
    const float* ln_kv_b = (const float*)d_in[4];
    const float* W_kv    = (const float*)d_in[5];
    const float* b_kv    = (const float*)d_in[6];
    const float* W_o     = (const float*)d_in[7];
    const float* b_o     = (const float*)d_in[8];
    const float* gamma   = (const float*)d_in[9];
    const float* ln_m_g  = (const float*)d_in[10];
    const float* ln_m_b  = (const float*)d_in[11];
    const float* W_emb   = (const float*)d_in[12];
    const float* b_emb   = (const float*)d_in[13];
    const float* W1      = (const float*)d_in[14];
    const float* b1      = (const float*)d_in[15];
    const float* W2      = (const float*)d_in[16];
    const float* b2      = (const float*)d_in[17];
    const float* gamma_mlp = (const float*)d_in[18];
    float* out = (float*)d_out;

    void *p_q, *p_akv, *p_kv, *p_attn, *p_x1, *p_h1;
    void *p_wkv, *p_wo, *p_w1c, *p_w2, *p_bc;
    cudaGetSymbolAddress(&p_q,    g_q);
    cudaGetSymbolAddress(&p_akv,  g_akv);
    cudaGetSymbolAddress(&p_kv,   g_kv);
    cudaGetSymbolAddress(&p_attn, g_attn);
    cudaGetSymbolAddress(&p_x1,   g_x1);
    cudaGetSymbolAddress(&p_h1,   g_h1);
    cudaGetSymbolAddress(&p_wkv,  g_wkv);
    cudaGetSymbolAddress(&p_wo,   g_wo);
    cudaGetSymbolAddress(&p_w1c,  g_w1c);
    cudaGetSymbolAddress(&p_w2,   g_w2);
    cudaGetSymbolAddress(&p_bc,   g_bcomb);

    cudaFuncSetAttribute(attn2_kernel, cudaFuncAttributeMaxDynamicSharedMemorySize, ATTN2_SMEM);
    cudaFuncSetAttribute(gemm2<512,  EPI_BIAS_F16>,  cudaFuncAttributeMaxDynamicSharedMemorySize, GEMM_SMEM);
    cudaFuncSetAttribute(gemm2<512,  EPI_GELU_F16>,  cudaFuncAttributeMaxDynamicSharedMemorySize, GEMM_SMEM);
    cudaFuncSetAttribute(gemm2<512,  EPI_RESID_F32>, cudaFuncAttributeMaxDynamicSharedMemorySize, GEMM_SMEM);
    cudaFuncSetAttribute(gemm2<1024, EPI_RESID_F32>, cudaFuncAttributeMaxDynamicSharedMemorySize, GEMM_SMEM);

    // 0a) W_comb (fp16 transposed) + b_comb
    wcomb_kernel<<<dim3(16, 8), 256>>>(W_emb, W1, (__half*)p_w1c);
    bcomb_kernel<<<4, 256>>>(b_emb, W1, b1, (float*)p_bc);

    // 0b) weight convert+transpose -> fp16 (tiled, coalesced; grid covers max dims)
    conv_w_all<<<dim3(32, 32, 3), 256>>>(W_kv, (__half*)p_wkv,
                                         W_o,  (__half*)p_wo,
                                         W2,   (__half*)p_w2);

    // 1) dual LN
    ln_kernel<<<NTOKS / 4, 256>>>(x, ln_q_g, ln_q_b, (__half*)p_q,
                                     ln_kv_g, ln_kv_b, (__half*)p_akv);

    // 2) kv = akv @ W_kv + b_kv
    gemm2<512, EPI_BIAS_F16><<<dim3(1024 / BN2, NTOKS / BM2), 256, GEMM_SMEM>>>(
        (const __half*)p_akv, (const __half*)p_wkv, b_kv,
        (__half*)p_kv, nullptr, nullptr, nullptr, 1024);

    // 3) windowed attention
    attn2_kernel<<<NGROUPS * SWIN * HEADS, 128, ATTN2_SMEM>>>(
        (const __half*)p_q, (const __half*)p_kv, (__half*)p_attn);

    // 4) x1 = x + gamma * (attn @ W_o + b_o)
    gemm2<512, EPI_RESID_F32><<<dim3(512 / BN2, NTOKS / BM2), 256, GEMM_SMEM>>>(
        (const __half*)p_attn, (const __half*)p_wo, b_o,
        nullptr, (float*)p_x1, x, gamma, 512);

    // 5) aemb = LN_m(x1)
    ln_kernel<<<NTOKS / 4, 256>>>((const float*)p_x1, ln_m_g, ln_m_b, (__half*)p_akv,
                                  nullptr, nullptr, nullptr);

    // 6) h1 = gelu(aemb @ W_comb + b_comb)
    gemm2<512, EPI_GELU_F16><<<dim3(1024 / BN2, NTOKS / BM2), 256, GEMM_SMEM>>>(
        (const __half*)p_akv, (const __half*)p_w1c, (const float*)p_bc,
        (__half*)p_h1, nullptr, nullptr, nullptr, 1024);

    // 7) out = x1 + gamma_mlp * (h1 @ W2 + b2)
    gemm2<1024, EPI_RESID_F32><<<dim3(512 / BN2, NTOKS / BM2), 256, GEMM_SMEM>>>(
        (const __half*)p_h1, (const __half*)p_w2, b2,
        nullptr, out, (const float*)p_x1, gamma_mlp, 512);
}

// round 16
// speedup vs baseline: 1.0852x; 1.0667x over previous
#include <cuda_runtime.h>
#include <cuda_fp16.h>
#include <mma.h>
#include <math.h>
#include <stdint.h>

using namespace nvcuda;

// Problem constants
#define NTOKS   65536
#define NGROUPS 8
#define SPER    8192
#define SWIN    128
#define NWIN    64
#define NKV     192
#define HEADS   8

// ---------------- device scratch ----------------
__device__ __align__(1024) __half g_q   [(size_t)NTOKS * 512];
__device__ __align__(1024) __half g_akv [(size_t)NTOKS * 512];
__device__ __align__(1024) __half g_kv  [(size_t)NTOKS * 1024];
__device__ __align__(1024) __half g_attn[(size_t)NTOKS * 512];
__device__ __align__(1024) float  g_x1  [(size_t)NTOKS * 512];
__device__ __align__(1024) __half g_h1  [(size_t)NTOKS * 1024];
__device__ __align__(1024) __half g_wkv [1024 * 512];
__device__ __align__(1024) __half g_wo  [512 * 512];
__device__ __align__(1024) __half g_w1c [1024 * 512];
__device__ __align__(1024) __half g_w2  [512 * 1024];
__device__ float g_bcomb[1024];

// ---------------- helpers ----------------
__device__ __forceinline__ uint32_t smem_u32(const void* p) {
    uint32_t a;
    asm("{ .reg .u64 t; cvta.to.shared.u64 t, %1; cvt.u32.u64 %0, t; }" : "=r"(a) : "l"(p));
    return a;
}
__device__ __forceinline__ void cp16_s(uint32_t daddr, const void* src) {
    asm volatile("cp.async.cg.shared.global [%0], [%1], 16;\n" :: "r"(daddr), "l"(src));
}
__device__ __forceinline__ void cp16(void* dst, const void* src) { cp16_s(smem_u32(dst), src); }
__device__ __forceinline__ void cp_commit() { asm volatile("cp.async.commit_group;\n"); }
template<int N> __device__ __forceinline__ void cp_wait() {
    asm volatile("cp.async.wait_group %0;\n" :: "n"(N));
}
__device__ __forceinline__ void ldsm4(uint32_t& r0, uint32_t& r1, uint32_t& r2, uint32_t& r3,
                                      uint32_t addr) {
    asm volatile("ldmatrix.sync.aligned.m8n8.x4.shared.b16 {%0,%1,%2,%3}, [%4];"
                 : "=r"(r0), "=r"(r1), "=r"(r2), "=r"(r3) : "r"(addr));
}
__device__ __forceinline__ void ldsm4t(uint32_t& r0, uint32_t& r1, uint32_t& r2, uint32_t& r3,
                                       uint32_t addr) {
    asm volatile("ldmatrix.sync.aligned.m8n8.x4.trans.shared.b16 {%0,%1,%2,%3}, [%4];"
                 : "=r"(r0), "=r"(r1), "=r"(r2), "=r"(r3) : "r"(addr));
}
__device__ __forceinline__ void hmma(float* d, const uint32_t* a, const uint32_t* b) {
    asm volatile("mma.sync.aligned.m16n8k16.row.col.f32.f16.f16.f32 "
                 "{%0,%1,%2,%3},{%4,%5,%6,%7},{%8,%9},{%0,%1,%2,%3};"
                 : "+f"(d[0]), "+f"(d[1]), "+f"(d[2]), "+f"(d[3])
                 : "r"(a[0]), "r"(a[1]), "r"(a[2]), "r"(a[3]), "r"(b[0]), "r"(b[1]));
}
__device__ __forceinline__ uint32_t h2u(float a, float b) {
    __half2 t = __floats2half2_rn(a, b);
    return *(uint32_t*)&t;
}

// ---------------- W_comb = W_emb @ W1, fp16 transposed ----------------
__global__ void __launch_bounds__(256)
wcomb_kernel(const float* __restrict__ We, const float* __restrict__ W1, __half* __restrict__ outT) {
    __shared__ float sa[64][65];
    __shared__ float sb[64][65];
    int bi = blockIdx.y * 64, bn = blockIdx.x * 64;
    int tid = threadIdx.x;
    int ti = (tid >> 4) * 4, tn = (tid & 15) * 4;
    float acc[4][4] = {};
    for (int j0 = 0; j0 < 512; j0 += 64) {
        for (int t = tid; t < 4096; t += 256) {
            int r = t >> 6, c = t & 63;
            sa[r][c] = We[(size_t)(bi + r) * 512 + j0 + c];
            sb[r][c] = W1[(size_t)(j0 + r) * 1024 + bn + c];
        }
        __syncthreads();
        for (int j = 0; j < 64; j++) {
            float b0 = sb[j][tn], b1 = sb[j][tn + 1], b2 = sb[j][tn + 2], b3 = sb[j][tn + 3];
            #pragma unroll
            for (int i = 0; i < 4; i++) {
                float av = sa[ti + i][j];
                acc[i][0] += av * b0; acc[i][1] += av * b1;
                acc[i][2] += av * b2; acc[i][3] += av * b3;
            }
        }
        __syncthreads();
    }
    #pragma unroll
    for (int i = 0; i < 4; i++)
        #pragma unroll
        for (int n = 0; n < 4; n++)
            outT[(size_t)(bn + tn + n) * 512 + (bi + ti + i)] = __float2half(acc[i][n]);
}

__global__ void bcomb_kernel(const float* __restrict__ b_emb, const float* __restrict__ W1,
                             const float* __restrict__ b1, float* __restrict__ out) {
    int n = blockIdx.x * 256 + threadIdx.x;
    if (n < 1024) {
        float acc = b1[n];
        for (int j = 0; j < 512; j++) acc += b_emb[j] * W1[j * 1024 + n];
        out[n] = acc;
    }
}

// ---------------- weight convert+transpose: smem-tiled, coalesced (round-15 proven) ----------------
__global__ void __launch_bounds__(256)
conv_w_all(const float* s0, __half* d0,
           const float* s1, __half* d1,
           const float* s2, __half* d2) {
    const float* src; __half* dst; int K, Nout;
    switch (blockIdx.z) {
        case 0: src = s0; dst = d0; K = 512;  Nout = 1024; break;
        case 1: src = s1; dst = d1; K = 512;  Nout = 512;  break;
        default:src = s2; dst = d2; K = 1024; Nout = 512;  break;
    }
    int k0 = blockIdx.x * 32;
    int n0 = blockIdx.y * 32;
    if (k0 >= K || n0 >= Nout) return;

    __shared__ float tile[32][33];
    int tx = threadIdx.x & 31;
    int ty = threadIdx.x >> 5;
    #pragma unroll
    for (int r = 0; r < 32; r += 8)
        tile[ty + r][tx] = src[(size_t)(k0 + ty + r) * Nout + n0 + tx];
    __syncthreads();
    #pragma unroll
    for (int r = 0; r < 32; r += 8)
        dst[(size_t)(n0 + ty + r) * K + k0 + tx] = __float2half(tile[tx][ty + r]);
}

// ---------------- LayerNorm ----------------
__global__ void __launch_bounds__(256)
ln_kernel(const float* __restrict__ x,
          const float* __restrict__ g1, const float* __restrict__ b1, __half* __restrict__ o1,
          const float* __restrict__ g2, const float* __restrict__ b2, __half* __restrict__ o2) {
    int tid = threadIdx.x;
    int g   = tid >> 6;
    int l   = tid & 63;
    size_t t = (size_t)blockIdx.x * 4 + g;
    int c = l * 8;

    const float4* px = (const float4*)(x + t * 512 + c);
    float4 v0 = px[0], v1 = px[1];
    float s = v0.x + v0.y + v0.z + v0.w + v1.x + v1.y + v1.z + v1.w;
    float q = v0.x*v0.x + v0.y*v0.y + v0.z*v0.z + v0.w*v0.w
            + v1.x*v1.x + v1.y*v1.y + v1.z*v1.z + v1.w*v1.w;
    #pragma unroll
    for (int o = 16; o; o >>= 1) {
        s += __shfl_xor_sync(0xffffffffu, s, o);
        q += __shfl_xor_sync(0xffffffffu, q, o);
    }
    __shared__ float ss[8], sq[8];
    int w = tid >> 5;
    if ((tid & 31) == 0) { ss[w] = s; sq[w] = q; }
    __syncthreads();
    s = ss[g * 2] + ss[g * 2 + 1];
    q = sq[g * 2] + sq[g * 2 + 1];
    float mean = s * (1.0f / 512.0f);
    float var  = q * (1.0f / 512.0f) - mean * mean;
    float rstd = rsqrtf(var + 1e-5f);

    float xh[8];
    xh[0]=(v0.x-mean)*rstd; xh[1]=(v0.y-mean)*rstd; xh[2]=(v0.z-mean)*rstd; xh[3]=(v0.w-mean)*rstd;
    xh[4]=(v1.x-mean)*rstd; xh[5]=(v1.y-mean)*rstd; xh[6]=(v1.z-mean)*rstd; xh[7]=(v1.w-mean)*rstd;

    {
        const float4 ga = *(const float4*)(g1 + c), gb = *(const float4*)(g1 + c + 4);
        const float4 ba = *(const float4*)(b1 + c), bb = *(const float4*)(b1 + c + 4);
        uint4 pk;
        pk.x = h2u(xh[0]*ga.x + ba.x, xh[1]*ga.y + ba.y);
        pk.y = h2u(xh[2]*ga.z + ba.z, xh[3]*ga.w + ba.w);
        pk.z = h2u(xh[4]*gb.x + bb.x, xh[5]*gb.y + bb.y);
        pk.w = h2u(xh[6]*gb.z + bb.z, xh[7]*gb.w + bb.w);
        *(uint4*)(o1 + t * 512 + c) = pk;
    }
    if (o2) {
        const float4 ga = *(const float4*)(g2 + c), gb = *(const float4*)(g2 + c + 4);
        const float4 ba = *(const float4*)(b2 + c), bb = *(const float4*)(b2 + c + 4);
        uint4 pk;
        pk.x = h2u(xh[0]*ga.x + ba.x, xh[1]*ga.y + ba.y);
        pk.y = h2u(xh[2]*ga.z + ba.z, xh[3]*ga.w + ba.w);
        pk.z = h2u(xh[4]*gb.x + bb.x, xh[5]*gb.y + bb.y);
        pk.w = h2u(xh[6]*gb.z + bb.z, xh[7]*gb.w + bb.w);
        *(uint4*)(o2 + t * 512 + c) = pk;
    }
}

// ---------------- WMMA GEMM, fp16 acc, BK=64, 3-stage prefetch, vectorized epilogue ----------------
enum { EPI_BIAS_F16 = 0, EPI_GELU_F16 = 1, EPI_RESID_F32 = 2 };

#define BM2 128
#define BN2 128
#define BK2 64
#define LDT 72
#define TILE_B (BM2 * LDT * 2)
#define STAGE_B (2 * TILE_B)
#define LDC2 136
#define GEMM_SMEM (3 * STAGE_B)   // 110592 B

template<int K, int EPI>
__global__ void __launch_bounds__(256)
gemm2(const __half* __restrict__ A,
      const __half* __restrict__ Bt,
      const float* __restrict__ bias,
      __half* __restrict__ outH,
      float* __restrict__ outF,
      const float* __restrict__ resid,
      const float* __restrict__ scale,
      int Nout) {
    extern __shared__ __align__(16) unsigned char dsm[];
    __half* sC = (__half*)dsm;

    int tid  = threadIdx.x;
    int warp = tid >> 5;
    int wm = warp & 3;
    int wn = warp >> 2;
    int mbase = blockIdx.y * BM2;
    int nbase = blockIdx.x * BN2;

    int r0c[4], c0c[4];
    #pragma unroll
    for (int it = 0; it < 4; it++) {
        int ch = tid + it * 256;
        r0c[it] = ch >> 3;
        c0c[it] = (ch & 7) << 3;
    }

    wmma::fragment<wmma::accumulator, 16, 16, 16, __half> acc[2][4];
    #pragma unroll
    for (int i = 0; i < 2; i++)
        #pragma unroll
        for (int j = 0; j < 4; j++)
            wmma::fill_fragment(acc[i][j], __float2half(0.0f));

    constexpr int KT = K / BK2;

    auto load_stage = [&](int kt, int st) {
        __half* sA = (__half*)(dsm + st * STAGE_B);
        __half* sB = (__half*)(dsm + st * STAGE_B + TILE_B);
        #pragma unroll
        for (int it = 0; it < 4; it++)
            cp16(sA + r0c[it] * LDT + c0c[it],
                 A + (size_t)(mbase + r0c[it]) * K + kt * BK2 + c0c[it]);
        #pragma unroll
        for (int it = 0; it < 4; it++)
            cp16(sB + r0c[it] * LDT + c0c[it],
                 Bt + (size_t)(nbase + r0c[it]) * K + kt * BK2 + c0c[it]);
    };

    #pragma unroll
    for (int p = 0; p < 3; p++) { load_stage(p, p); cp_commit(); }

    for (int kt = 0; kt < KT; kt++) {
        if (kt + 2 < KT)      cp_wait<2>();
        else if (kt + 1 < KT) cp_wait<1>();
        else                  cp_wait<0>();
        __syncthreads();
        int b = kt % 3;
        __half* sA = (__half*)(dsm + b * STAGE_B);
        __half* sB = (__half*)(dsm + b * STAGE_B + TILE_B);
        #pragma unroll
        for (int ks = 0; ks < BK2; ks += 16) {
            wmma::fragment<wmma::matrix_a, 16, 16, 16, __half, wmma::row_major> af[2];
            wmma::fragment<wmma::matrix_b, 16, 16, 16, __half, wmma::col_major> bf[4];
            wmma::load_matrix_sync(af[0], sA + (wm * 32)      * LDT + ks, LDT);
            wmma::load_matrix_sync(af[1], sA + (wm * 32 + 16) * LDT + ks, LDT);
            #pragma unroll
            for (int j = 0; j < 4; j++)
                wmma::load_matrix_sync(bf[j], sB + (wn * 64 + j * 16) * LDT + ks, LDT);
            #pragma unroll
            for (int i = 0; i < 2; i++)
                #pragma unroll
                for (int j = 0; j < 4; j++)
                    wmma::mma_sync(acc[i][j], af[i], bf[j], acc[i][j]);
        }
        __syncthreads();
        if (kt + 3 < KT) {
            load_stage(kt + 3, b);
            cp_commit();
        }
    }

    #pragma unroll
    for (int i = 0; i < 2; i++)
        #pragma unroll
        for (int j = 0; j < 4; j++)
            wmma::store_matrix_sync(sC + (wm * 32 + i * 16) * LDC2 + wn * 64 + j * 16,
                                    acc[i][j], LDC2, wmma::mem_row_major);
    __syncthreads();

    if (EPI == EPI_RESID_F32) {
        // 4096 float4-chunks of 4 cols; 16 per thread
        #pragma unroll 4
        for (int e = tid; e < BM2 * BN2 / 4; e += 256) {
            int r = e >> 5;            // 32 chunks per 128-col row
            int c = (e & 31) << 2;
            __half hv[4];
            *(uint2*)hv = *(const uint2*)(sC + r * LDC2 + c);
            int gr = mbase + r;
            int gc = nbase + c;
            const float4 rv = *(const float4*)(resid + (size_t)gr * Nout + gc);
            float4 ov;
            ov.x = rv.x + scale[gc]     * (__half2float(hv[0]) + bias[gc]);
            ov.y = rv.y + scale[gc + 1] * (__half2float(hv[1]) + bias[gc + 1]);
            ov.z = rv.z + scale[gc + 2] * (__half2float(hv[2]) + bias[gc + 2]);
            ov.w = rv.w + scale[gc + 3] * (__half2float(hv[3]) + bias[gc + 3]);
            *(float4*)(outF + (size_t)gr * Nout + gc) = ov;
        }
    } else {
        // 2048 uint4-chunks of 8 halfs; 8 per thread
        #pragma unroll 4
        for (int e = tid; e < BM2 * BN2 / 8; e += 256) {
            int r = e >> 4;            // 16 chunks per row
            int c = (e & 15) << 3;
            __half hv[8];
            *(uint4*)hv = *(const uint4*)(sC + r * LDC2 + c);
            int gr = mbase + r;
            int gc = nbase + c;
            __half ov[8];
            #pragma unroll
            for (int j = 0; j < 8; j++) {
                float t = __half2float(hv[j]) + bias[gc + j];
                if (EPI == EPI_GELU_F16) {
                    float u = 0.7978845608028654f * (t + 0.044715f * t * t * t);
                    float th;
                    asm("tanh.approx.f32 %0, %1;" : "=f"(th) : "f"(u));
                    t = 0.5f * t * (1.0f + th);
                }
                ov[j] = __float2half(t);
            }
            *(uint4*)(outH + (size_t)gr * Nout + gc) = *(uint4*)ov;
        }
    }
}

// ---------------- attention: register softmax, V overlapped (round-13 proven) ----------------
#define LDQ 72
#define ATTN2_SMEM ((64 + 192 + 192) * LDQ * 2)   // 64512 bytes

__global__ void __launch_bounds__(128)
attn2_kernel(const __half* __restrict__ q,
             const __half* __restrict__ kv,
             __half* __restrict__ attn_out) {
    extern __shared__ __align__(16) unsigned char dsm[];
    __half* sQ = (__half*)dsm;
    __half* sK = sQ + 64 * LDQ;
    __half* sV = sK + NKV * LDQ;

    int bid  = blockIdx.x;
    int head = bid & 7;
    int win  = bid >> 3;
    int g8   = win >> 7;
    int sw   = win & 127;
    size_t tbase = (size_t)g8 * SPER + (size_t)sw * NWIN;

    int tid  = threadIdx.x;
    bool valid0 = (sw > 0);
    bool valid2 = (sw < SWIN - 1);
    int cl0 = valid0 ? (sw - 1) : 0;
    int cl2 = valid2 ? (sw + 1) : (SWIN - 1);
    size_t kb0 = (size_t)g8 * SPER + (size_t)cl0 * NWIN;
    size_t kb2 = (size_t)g8 * SPER + (size_t)cl2 * NWIN;

    #pragma unroll
    for (int it = 0; it < 4; it++) {
        int ch = tid + it * 128;
        int r = ch >> 3, cc = (ch & 7) << 3;
        cp16(sQ + r * LDQ + cc, q + (tbase + r) * 512 + head * 64 + cc);
    }
    #pragma unroll
    for (int it = 0; it < 12; it++) {
        int ch = tid + it * 128;
        int r = ch >> 3, cc = (ch & 7) << 3;
        int nb = r >> 6, lr2 = r & 63;
        size_t tok = (nb == 0 ? kb0 : (nb == 1 ? tbase : kb2)) + lr2;
        cp16(sK + r * LDQ + cc, kv + tok * 1024 + head * 64 + cc);
    }
    cp_commit();
    #pragma unroll
    for (int it = 0; it < 12; it++) {
        int ch = tid + it * 128;
        int r = ch >> 3, cc = (ch & 7) << 3;
        int nb = r >> 6, lr2 = r & 63;
        size_t tok = (nb == 0 ? kb0 : (nb == 1 ? tbase : kb2)) + lr2;
        cp16(sV + r * LDQ + cc, kv + tok * 1024 + 512 + head * 64 + cc);
    }
    cp_commit();

    cp_wait<1>();
    __syncthreads();

    int warp = tid >> 5;
    int lane = tid & 31;
    int g    = lane >> 2;
    int tig  = lane & 3;
    int lr   = lane & 7;
    int lm   = lane >> 3;
    int r0   = warp * 16;

    uint32_t aq[4][4];
    #pragma unroll
    for (int kk = 0; kk < 4; kk++) {
        int row = r0 + lr + ((lm & 1) << 3);
        int col = kk * 16 + ((lm & 2) << 2);
        ldsm4(aq[kk][0], aq[kk][1], aq[kk][2], aq[kk][3], smem_u32(sQ + row * LDQ + col));
    }

    float sc[24][4];
    #pragma unroll
    for (int j = 0; j < 24; j++) { sc[j][0]=0.f; sc[j][1]=0.f; sc[j][2]=0.f; sc[j][3]=0.f; }

    #pragma unroll
    for (int nb = 0; nb < 12; nb++) {
        #pragma unroll
        for (int kk = 0; kk < 4; kk++) {
            int row = nb * 16 + lr + ((lm & 2) << 2);
            int col = kk * 16 + ((lm & 1) << 3);
            uint32_t b4[4];
            ldsm4(b4[0], b4[1], b4[2], b4[3], smem_u32(sK + row * LDQ + col));
            hmma(sc[2 * nb],     aq[kk], &b4[0]);
            hmma(sc[2 * nb + 1], aq[kk], &b4[2]);
        }
    }

    int lo = valid0 ? 0   : 64;
    int hi = valid2 ? 192 : 128;
    float mx0 = -3.0e38f, mx1 = -3.0e38f;
    #pragma unroll
    for (int j = 0; j < 24; j++) {
        int c0 = j * 8 + 2 * tig;
        if (c0 >= lo && c0 < hi) {
            mx0 = fmaxf(mx0, fmaxf(sc[j][0], sc[j][1]));
            mx1 = fmaxf(mx1, fmaxf(sc[j][2], sc[j][3]));
        }
    }
    mx0 = fmaxf(mx0, __shfl_xor_sync(0xffffffffu, mx0, 1));
    mx0 = fmaxf(mx0, __shfl_xor_sync(0xffffffffu, mx0, 2));
    mx1 = fmaxf(mx1, __shfl_xor_sync(0xffffffffu, mx1, 1));
    mx1 = fmaxf(mx1, __shfl_xor_sync(0xffffffffu, mx1, 2));

    float sum0 = 0.f, sum1 = 0.f;
    #pragma unroll
    for (int j = 0; j < 24; j++) {
        int c0 = j * 8 + 2 * tig;
        bool ok = (c0 >= lo) && (c0 < hi);
        float e0 = ok ? __expf((sc[j][0] - mx0) * 0.125f) : 0.f;
        float e1 = ok ? __expf((sc[j][1] - mx0) * 0.125f) : 0.f;
        float e2 = ok ? __expf((sc[j][2] - mx1) * 0.125f) : 0.f;
        float e3 = ok ? __expf((sc[j][3] - mx1) * 0.125f) : 0.f;
        sc[j][0] = e0; sc[j][1] = e1; sc[j][2] = e2; sc[j][3] = e3;
        sum0 += e0 + e1;
        sum1 += e2 + e3;
    }
    sum0 += __shfl_xor_sync(0xffffffffu, sum0, 1);
    sum0 += __shfl_xor_sync(0xffffffffu, sum0, 2);
    sum1 += __shfl_xor_sync(0xffffffffu, sum1, 1);
    sum1 += __shfl_xor_sync(0xffffffffu, sum1, 2);
    float inv0 = 1.0f / sum0;
    float inv1 = 1.0f / sum1;

    cp_wait<0>();
    __syncthreads();

    float oa[8][4];
    #pragma unroll
    for (int j = 0; j < 8; j++) { oa[j][0]=0.f; oa[j][1]=0.f; oa[j][2]=0.f; oa[j][3]=0.f; }

    #pragma unroll
    for (int kk2 = 0; kk2 < 12; kk2++) {
        uint32_t ap[4];
        ap[0] = h2u(sc[2*kk2][0]   * inv0, sc[2*kk2][1]   * inv0);
        ap[1] = h2u(sc[2*kk2][2]   * inv1, sc[2*kk2][3]   * inv1);
        ap[2] = h2u(sc[2*kk2+1][0] * inv0, sc[2*kk2+1][1] * inv0);
        ap[3] = h2u(sc[2*kk2+1][2] * inv1, sc[2*kk2+1][3] * inv1);
        #pragma unroll
        for (int nb2 = 0; nb2 < 4; nb2++) {
            int row = kk2 * 16 + lr + ((lm & 1) << 3);
            int col = nb2 * 16 + ((lm & 2) << 2);
            uint32_t b4[4];
            ldsm4t(b4[0], b4[1], b4[2], b4[3], smem_u32(sV + row * LDQ + col));
            hmma(oa[2 * nb2],     ap, &b4[0]);
            hmma(oa[2 * nb2 + 1], ap, &b4[2]);
        }
    }

    size_t rowg = tbase + r0 + g;
    #pragma unroll
    for (int j2 = 0; j2 < 8; j2++) {
        *(uint32_t*)(attn_out + rowg * 512 + head * 64 + j2 * 8 + 2 * tig) =
            h2u(oa[j2][0], oa[j2][1]);
        *(uint32_t*)(attn_out + (rowg + 8) * 512 + head * 64 + j2 * 8 + 2 * tig) =
            h2u(oa[j2][2], oa[j2][3]);
    }
}

// ---------------- host launcher ----------------
extern "C" void kernel_launch(void* const* d_in, const int* in_sizes, int n_in,
                              void* d_out, int out_size) {
    (void)in_sizes; (void)n_in; (void)out_size;
    const float* x       = (const float*)d_in[0];
    const float* ln_q_g  = (const float*)d_in[1];
    const float* ln_q_b  = (const float*)d_in[2];
    const float* ln_kv_g = (const float*)d_in[3];
    const float* ln_kv_b = (const float*)d_in[4];
    const float* W_kv    = (const float*)d_in[5];
    const float* b_kv    = (const float*)d_in[6];
    const float* W_o     = (const float*)d_in[7];
    const float* b_o     = (const float*)d_in[8];
    const float* gamma   = (const float*)d_in[9];
    const float* ln_m_g  = (const float*)d_in[10];
    const float* ln_m_b  = (const float*)d_in[11];
    const float* W_emb   = (const float*)d_in[12];
    const float* b_emb   = (const float*)d_in[13];
    const float* W1      = (const float*)d_in[14];
    const float* b1      = (const float*)d_in[15];
    const float* W2      = (const float*)d_in[16];
    const float* b2      = (const float*)d_in[17];
    const float* gamma_mlp = (const float*)d_in[18];
    float* out = (float*)d_out;

    void *p_q, *p_akv, *p_kv, *p_attn, *p_x1, *p_h1;
    void *p_wkv, *p_wo, *p_w1c, *p_w2, *p_bc;
    cudaGetSymbolAddress(&p_q,    g_q);
    cudaGetSymbolAddress(&p_akv,  g_akv);
    cudaGetSymbolAddress(&p_kv,   g_kv);
    cudaGetSymbolAddress(&p_attn, g_attn);
    cudaGetSymbolAddress(&p_x1,   g_x1);
    cudaGetSymbolAddress(&p_h1,   g_h1);
    cudaGetSymbolAddress(&p_wkv,  g_wkv);
    cudaGetSymbolAddress(&p_wo,   g_wo);
    cudaGetSymbolAddress(&p_w1c,  g_w1c);
    cudaGetSymbolAddress(&p_w2,   g_w2);
    cudaGetSymbolAddress(&p_bc,   g_bcomb);

    cudaFuncSetAttribute(attn2_kernel, cudaFuncAttributeMaxDynamicSharedMemorySize, ATTN2_SMEM);
    cudaFuncSetAttribute(gemm2<512,  EPI_BIAS_F16>,  cudaFuncAttributeMaxDynamicSharedMemorySize, GEMM_SMEM);
    cudaFuncSetAttribute(gemm2<512,  EPI_GELU_F16>,  cudaFuncAttributeMaxDynamicSharedMemorySize, GEMM_SMEM);
    cudaFuncSetAttribute(gemm2<512,  EPI_RESID_F32>, cudaFuncAttributeMaxDynamicSharedMemorySize, GEMM_SMEM);
    cudaFuncSetAttribute(gemm2<1024, EPI_RESID_F32>, cudaFuncAttributeMaxDynamicSharedMemorySize, GEMM_SMEM);

    // 0a) W_comb (fp16 transposed) + b_comb
    wcomb_kernel<<<dim3(16, 8), 256>>>(W_emb, W1, (__half*)p_w1c);
    bcomb_kernel<<<4, 256>>>(b_emb, W1, b1, (float*)p_bc);

    // 0b) weight convert+transpose -> fp16 (tiled, coalesced)
    conv_w_all<<<dim3(32, 32, 3), 256>>>(W_kv, (__half*)p_wkv,
                                         W_o,  (__half*)p_wo,
                                         W2,   (__half*)p_w2);

    // 1) dual LN
    ln_kernel<<<NTOKS / 4, 256>>>(x, ln_q_g, ln_q_b, (__half*)p_q,
                                     ln_kv_g, ln_kv_b, (__half*)p_akv);

    // 2) kv = akv @ W_kv + b_kv
    gemm2<512, EPI_BIAS_F16><<<dim3(1024 / BN2, NTOKS / BM2), 256, GEMM_SMEM>>>(
        (const __half*)p_akv, (const __half*)p_wkv, b_kv,
        (__half*)p_kv, nullptr, nullptr, nullptr, 1024);

    // 3) windowed attention
    attn2_kernel<<<NGROUPS * SWIN * HEADS, 128, ATTN2_SMEM>>>(
        (const __half*)p_q, (const __half*)p_kv, (__half*)p_attn);

    // 4) x1 = x + gamma * (attn @ W_o + b_o)
    gemm2<512, EPI_RESID_F32><<<dim3(512 / BN2, NTOKS / BM2), 256, GEMM_SMEM>>>(
        (const __half*)p_attn, (const __half*)p_wo, b_o,
        nullptr, (float*)p_x1, x, gamma, 512);

    // 5) aemb = LN_m(x1)
    ln_kernel<<<NTOKS / 4, 256>>>((const float*)p_x1, ln_m_g, ln_m_b, (__half*)p_akv,
                                  nullptr, nullptr, nullptr);

    // 6) h1 = gelu(aemb @ W_comb + b_comb)
    gemm2<512, EPI_GELU_F16><<<dim3(1024 / BN2, NTOKS / BM2), 256, GEMM_SMEM>>>(
        (const __half*)p_akv, (const __half*)p_w1c, (const float*)p_bc,
        (__half*)p_h1, nullptr, nullptr, nullptr, 1024);

    // 7) out = x1 + gamma_mlp * (h1 @ W2 + b2)
    gemm2<1024, EPI_RESID_F32><<<dim3(512 / BN2, NTOKS / BM2), 256, GEMM_SMEM>>>(
        (const __half*)p_h1, (const __half*)p_w2, b2,
        nullptr, out, (const float*)p_x1, gamma_mlp, 512);
}